// round 1
// baseline (speedup 1.0000x reference)
#include <cuda_runtime.h>
#include <math.h>

// Problem shape (fixed by the reference setup_inputs)
#define BATCH 2
#define DDIM  1024
#define NST   16
#define LEN   2048
#define ROWS  (BATCH * DDIM)   // 2048 (b,d) rows
#define RPB   16               // rows per block (8 warps x 2 rows)
#define TT    128              // time tile staged in smem
#define PITCH 17               // smem pitch (bank-conflict-free [t][n] reads)

// Scratch (no cudaMalloc allowed): softplus(delta), silu(z)
__device__ float g_sp[ROWS * LEN];
__device__ float g_sz[ROWS * LEN];

__device__ __forceinline__ float ex2f(float x) {
    float y;
    asm("ex2.approx.ftz.f32 %0, %1;" : "=f"(y) : "f"(x));
    return y;
}

__device__ __forceinline__ float softplus_f(float x) {
    // matches jax.nn.softplus within fp32 tolerance; stable for large |x|
    return (x > 20.0f) ? x : log1pf(expf(x));
}

__device__ __forceinline__ float silu_f(float x) {
    return x / (1.0f + expf(-x));
}

// Packed elementwise pass: every MUFU here serves 32 useful lanes.
__global__ void __launch_bounds__(256) pre_kernel(const float* __restrict__ delta,
                                                  const float* __restrict__ z) {
    int i = (blockIdx.x * blockDim.x + threadIdx.x) * 4;
    float4 dd = *reinterpret_cast<const float4*>(delta + i);
    float4 zz = *reinterpret_cast<const float4*>(z + i);
    float4 sp, sz;
    sp.x = softplus_f(dd.x); sp.y = softplus_f(dd.y);
    sp.z = softplus_f(dd.z); sp.w = softplus_f(dd.w);
    sz.x = silu_f(zz.x); sz.y = silu_f(zz.y);
    sz.z = silu_f(zz.z); sz.w = silu_f(zz.w);
    *reinterpret_cast<float4*>(g_sp + i) = sp;
    *reinterpret_cast<float4*>(g_sz + i) = sz;
}

// Main scan: warp = 2 rows, lane = state n (0..15) within each 16-lane half.
__global__ void __launch_bounds__(256) scan_kernel(const float* __restrict__ u,
                                                   const float* __restrict__ A,
                                                   const float* __restrict__ B,
                                                   const float* __restrict__ C,
                                                   const float* __restrict__ Dv,
                                                   float* __restrict__ y) {
    __shared__ float Bsm[TT][PITCH];
    __shared__ float Csm[TT][PITCH];

    const int tid  = threadIdx.x;
    const int lane = tid & 31;
    const int warp = tid >> 5;
    const int n    = lane & 15;
    const int half = lane >> 4;

    const int row = blockIdx.x * RPB + warp * 2 + half;  // global (b,d) row
    const int b   = row / DDIM;
    const int d   = row - b * DDIM;

    const float A2 = A[d * NST + n] * 1.4426950408889634f;  // A * log2(e)
    const float Dd = Dv[d];

    const float* __restrict__ sp_r = g_sp + (size_t)row * LEN;
    const float* __restrict__ sz_r = g_sz + (size_t)row * LEN;
    const float* __restrict__ u_r  = u    + (size_t)row * LEN;
    float*       __restrict__ y_r  = y    + (size_t)row * LEN;
    const float* __restrict__ B_b  = B + (size_t)b * NST * LEN;
    const float* __restrict__ C_b  = C + (size_t)b * NST * LEN;

    float h = 0.0f;

    for (int t0 = 0; t0 < LEN; t0 += TT) {
        __syncthreads();  // previous tile's smem reads done
        // Stage B,C tile transposed to [t][n]: coalesced LDG.128 along t.
        #pragma unroll
        for (int i = tid; i < NST * (TT / 4); i += 256) {
            const int nn = i >> 5;          // state index 0..15
            const int t4 = (i & 31) << 2;   // t offset 0,4,...,124
            float4 b4 = *reinterpret_cast<const float4*>(B_b + nn * LEN + t0 + t4);
            float4 c4 = *reinterpret_cast<const float4*>(C_b + nn * LEN + t0 + t4);
            Bsm[t4 + 0][nn] = b4.x; Bsm[t4 + 1][nn] = b4.y;
            Bsm[t4 + 2][nn] = b4.z; Bsm[t4 + 3][nn] = b4.w;
            Csm[t4 + 0][nn] = c4.x; Csm[t4 + 1][nn] = c4.y;
            Csm[t4 + 2][nn] = c4.z; Csm[t4 + 3][nn] = c4.w;
        }
        __syncthreads();

        #pragma unroll 2
        for (int tj = 0; tj < TT; tj += 4) {
            const int t = t0 + tj;
            float4 sp4 = *reinterpret_cast<const float4*>(sp_r + t);
            float4 u4  = *reinterpret_cast<const float4*>(u_r + t);
            float4 sz4 = *reinterpret_cast<const float4*>(sz_r + t);
            float r0, r1, r2, r3;

            {
                float a = ex2f(sp4.x * A2);
                h = fmaf(a, h, (sp4.x * u4.x) * Bsm[tj + 0][n]);
                float p = Csm[tj + 0][n] * h;
                p += __shfl_xor_sync(0xffffffffu, p, 8);
                p += __shfl_xor_sync(0xffffffffu, p, 4);
                p += __shfl_xor_sync(0xffffffffu, p, 2);
                p += __shfl_xor_sync(0xffffffffu, p, 1);
                r0 = (p + u4.x * Dd) * sz4.x;
            }
            {
                float a = ex2f(sp4.y * A2);
                h = fmaf(a, h, (sp4.y * u4.y) * Bsm[tj + 1][n]);
                float p = Csm[tj + 1][n] * h;
                p += __shfl_xor_sync(0xffffffffu, p, 8);
                p += __shfl_xor_sync(0xffffffffu, p, 4);
                p += __shfl_xor_sync(0xffffffffu, p, 2);
                p += __shfl_xor_sync(0xffffffffu, p, 1);
                r1 = (p + u4.y * Dd) * sz4.y;
            }
            {
                float a = ex2f(sp4.z * A2);
                h = fmaf(a, h, (sp4.z * u4.z) * Bsm[tj + 2][n]);
                float p = Csm[tj + 2][n] * h;
                p += __shfl_xor_sync(0xffffffffu, p, 8);
                p += __shfl_xor_sync(0xffffffffu, p, 4);
                p += __shfl_xor_sync(0xffffffffu, p, 2);
                p += __shfl_xor_sync(0xffffffffu, p, 1);
                r2 = (p + u4.z * Dd) * sz4.z;
            }
            {
                float a = ex2f(sp4.w * A2);
                h = fmaf(a, h, (sp4.w * u4.w) * Bsm[tj + 3][n]);
                float p = Csm[tj + 3][n] * h;
                p += __shfl_xor_sync(0xffffffffu, p, 8);
                p += __shfl_xor_sync(0xffffffffu, p, 4);
                p += __shfl_xor_sync(0xffffffffu, p, 2);
                p += __shfl_xor_sync(0xffffffffu, p, 1);
                r3 = (p + u4.w * Dd) * sz4.w;
            }

            if (n == 0) {  // lanes 0 and 16 hold the two rows' sums
                *reinterpret_cast<float4*>(y_r + t) = make_float4(r0, r1, r2, r3);
            }
        }
    }
}

extern "C" void kernel_launch(void* const* d_in, const int* in_sizes, int n_in,
                              void* d_out, int out_size) {
    // metadata order: u, delta, A, B, C, D, z, delta_softplus
    const float* u     = (const float*)d_in[0];
    const float* delta = (const float*)d_in[1];
    const float* A     = (const float*)d_in[2];
    const float* B     = (const float*)d_in[3];
    const float* C     = (const float*)d_in[4];
    const float* D     = (const float*)d_in[5];
    const float* z     = (const float*)d_in[6];
    float* y = (float*)d_out;

    // 4.2M elements, 4 per thread, 256 threads/block -> 4096 blocks
    pre_kernel<<<(ROWS * LEN) / (256 * 4), 256>>>(delta, z);
    // 2048 rows / 16 rows-per-block -> 128 blocks, all resident
    scan_kernel<<<ROWS / RPB, 256>>>(u, A, B, C, D, y);
}

// round 2
// speedup vs baseline: 1.0029x; 1.0029x over previous
#include <cuda_runtime.h>
#include <math.h>

// Problem shape (fixed by the reference setup_inputs)
#define BATCH 2
#define DDIM  1024
#define NST   16
#define LEN   2048
#define ROWS  (BATCH * DDIM)   // 2048 (b,d) rows
#define RPB   16               // rows per block (8 warps x 2 rows)
#define TT    128              // time tile staged in smem
#define PITCH 17               // smem pitch (bank-conflict-free [t][n] reads)

// Scratch (no cudaMalloc allowed): softplus(delta), silu(z)
__device__ float g_sp[ROWS * LEN];
__device__ float g_sz[ROWS * LEN];

__device__ __forceinline__ float ex2f(float x) {
    float y;
    asm("ex2.approx.ftz.f32 %0, %1;" : "=f"(y) : "f"(x));
    return y;
}

__device__ __forceinline__ float softplus_f(float x) {
    // matches jax.nn.softplus within fp32 tolerance; stable for large |x|
    return (x > 20.0f) ? x : log1pf(expf(x));
}

__device__ __forceinline__ float silu_f(float x) {
    return x / (1.0f + expf(-x));
}

// Packed elementwise pass: every MUFU here serves 32 useful lanes.
__global__ void __launch_bounds__(256) pre_kernel(const float* __restrict__ delta,
                                                  const float* __restrict__ z) {
    int i = (blockIdx.x * blockDim.x + threadIdx.x) * 4;
    float4 dd = *reinterpret_cast<const float4*>(delta + i);
    float4 zz = *reinterpret_cast<const float4*>(z + i);
    float4 sp, sz;
    sp.x = softplus_f(dd.x); sp.y = softplus_f(dd.y);
    sp.z = softplus_f(dd.z); sp.w = softplus_f(dd.w);
    sz.x = silu_f(zz.x); sz.y = silu_f(zz.y);
    sz.z = silu_f(zz.z); sz.w = silu_f(zz.w);
    *reinterpret_cast<float4*>(g_sp + i) = sp;
    *reinterpret_cast<float4*>(g_sz + i) = sz;
}

// Main scan: warp = 2 rows, lane = state n (0..15) within each 16-lane half.
__global__ void __launch_bounds__(256) scan_kernel(const float* __restrict__ u,
                                                   const float* __restrict__ A,
                                                   const float* __restrict__ B,
                                                   const float* __restrict__ C,
                                                   const float* __restrict__ Dv,
                                                   float* __restrict__ y) {
    __shared__ float Bsm[TT][PITCH];
    __shared__ float Csm[TT][PITCH];

    const int tid  = threadIdx.x;
    const int lane = tid & 31;
    const int warp = tid >> 5;
    const int n    = lane & 15;
    const int half = lane >> 4;

    const int row = blockIdx.x * RPB + warp * 2 + half;  // global (b,d) row
    const int b   = row / DDIM;
    const int d   = row - b * DDIM;

    const float A2 = A[d * NST + n] * 1.4426950408889634f;  // A * log2(e)
    const float Dd = Dv[d];

    const float* __restrict__ sp_r = g_sp + (size_t)row * LEN;
    const float* __restrict__ sz_r = g_sz + (size_t)row * LEN;
    const float* __restrict__ u_r  = u    + (size_t)row * LEN;
    float*       __restrict__ y_r  = y    + (size_t)row * LEN;
    const float* __restrict__ B_b  = B + (size_t)b * NST * LEN;
    const float* __restrict__ C_b  = C + (size_t)b * NST * LEN;

    float h = 0.0f;

    for (int t0 = 0; t0 < LEN; t0 += TT) {
        __syncthreads();  // previous tile's smem reads done
        // Stage B,C tile transposed to [t][n]: coalesced LDG.128 along t.
        #pragma unroll
        for (int i = tid; i < NST * (TT / 4); i += 256) {
            const int nn = i >> 5;          // state index 0..15
            const int t4 = (i & 31) << 2;   // t offset 0,4,...,124
            float4 b4 = *reinterpret_cast<const float4*>(B_b + nn * LEN + t0 + t4);
            float4 c4 = *reinterpret_cast<const float4*>(C_b + nn * LEN + t0 + t4);
            Bsm[t4 + 0][nn] = b4.x; Bsm[t4 + 1][nn] = b4.y;
            Bsm[t4 + 2][nn] = b4.z; Bsm[t4 + 3][nn] = b4.w;
            Csm[t4 + 0][nn] = c4.x; Csm[t4 + 1][nn] = c4.y;
            Csm[t4 + 2][nn] = c4.z; Csm[t4 + 3][nn] = c4.w;
        }
        __syncthreads();

        #pragma unroll 2
        for (int tj = 0; tj < TT; tj += 4) {
            const int t = t0 + tj;
            float4 sp4 = *reinterpret_cast<const float4*>(sp_r + t);
            float4 u4  = *reinterpret_cast<const float4*>(u_r + t);
            float4 sz4 = *reinterpret_cast<const float4*>(sz_r + t);
            float r0, r1, r2, r3;

            {
                float a = ex2f(sp4.x * A2);
                h = fmaf(a, h, (sp4.x * u4.x) * Bsm[tj + 0][n]);
                float p = Csm[tj + 0][n] * h;
                p += __shfl_xor_sync(0xffffffffu, p, 8);
                p += __shfl_xor_sync(0xffffffffu, p, 4);
                p += __shfl_xor_sync(0xffffffffu, p, 2);
                p += __shfl_xor_sync(0xffffffffu, p, 1);
                r0 = (p + u4.x * Dd) * sz4.x;
            }
            {
                float a = ex2f(sp4.y * A2);
                h = fmaf(a, h, (sp4.y * u4.y) * Bsm[tj + 1][n]);
                float p = Csm[tj + 1][n] * h;
                p += __shfl_xor_sync(0xffffffffu, p, 8);
                p += __shfl_xor_sync(0xffffffffu, p, 4);
                p += __shfl_xor_sync(0xffffffffu, p, 2);
                p += __shfl_xor_sync(0xffffffffu, p, 1);
                r1 = (p + u4.y * Dd) * sz4.y;
            }
            {
                float a = ex2f(sp4.z * A2);
                h = fmaf(a, h, (sp4.z * u4.z) * Bsm[tj + 2][n]);
                float p = Csm[tj + 2][n] * h;
                p += __shfl_xor_sync(0xffffffffu, p, 8);
                p += __shfl_xor_sync(0xffffffffu, p, 4);
                p += __shfl_xor_sync(0xffffffffu, p, 2);
                p += __shfl_xor_sync(0xffffffffu, p, 1);
                r2 = (p + u4.z * Dd) * sz4.z;
            }
            {
                float a = ex2f(sp4.w * A2);
                h = fmaf(a, h, (sp4.w * u4.w) * Bsm[tj + 3][n]);
                float p = Csm[tj + 3][n] * h;
                p += __shfl_xor_sync(0xffffffffu, p, 8);
                p += __shfl_xor_sync(0xffffffffu, p, 4);
                p += __shfl_xor_sync(0xffffffffu, p, 2);
                p += __shfl_xor_sync(0xffffffffu, p, 1);
                r3 = (p + u4.w * Dd) * sz4.w;
            }

            if (n == 0) {  // lanes 0 and 16 hold the two rows' sums
                *reinterpret_cast<float4*>(y_r + t) = make_float4(r0, r1, r2, r3);
            }
        }
    }
}

extern "C" void kernel_launch(void* const* d_in, const int* in_sizes, int n_in,
                              void* d_out, int out_size) {
    // metadata order: u, delta, A, B, C, D, z, delta_softplus
    const float* u     = (const float*)d_in[0];
    const float* delta = (const float*)d_in[1];
    const float* A     = (const float*)d_in[2];
    const float* B     = (const float*)d_in[3];
    const float* C     = (const float*)d_in[4];
    const float* D     = (const float*)d_in[5];
    const float* z     = (const float*)d_in[6];
    float* y = (float*)d_out;

    // 4.2M elements, 4 per thread, 256 threads/block -> 4096 blocks
    pre_kernel<<<(ROWS * LEN) / (256 * 4), 256>>>(delta, z);
    // 2048 rows / 16 rows-per-block -> 128 blocks, all resident
    scan_kernel<<<ROWS / RPB, 256>>>(u, A, B, C, D, y);
}

// round 3
// speedup vs baseline: 1.6551x; 1.6503x over previous
#include <cuda_runtime.h>
#include <math.h>

// Problem shape (fixed by reference setup_inputs)
#define BATCH  2
#define DDIM   1024
#define NST    16
#define LEN    2048
#define ROWS   (BATCH * DDIM)    // 2048 (b,d) rows
#define CHUNKS 16
#define CLEN   (LEN / CHUNKS)    // 128 timesteps per chunk
#define PITCH  17                // conflict-free smem pitch
#define LOG2E  1.4426950408889634f

// Scratch (no cudaMalloc allowed)
__device__ float g_sp[ROWS * LEN];              // softplus(delta)
__device__ float g_sz[ROWS * LEN];              // silu(z)
__device__ float g_hloc[ROWS * CHUNKS * NST];   // per-chunk local final state
__device__ float g_sumsp[ROWS * CHUNKS];        // per-chunk sum of softplus
__device__ float g_carry[ROWS * CHUNKS * NST];  // carry-in state per chunk

__device__ __forceinline__ float ex2f(float x) {
    float y;
    asm("ex2.approx.ftz.f32 %0, %1;" : "=f"(y) : "f"(x));
    return y;
}
__device__ __forceinline__ float softplus_f(float x) {
    return (x > 20.0f) ? x : log1pf(expf(x));
}
__device__ __forceinline__ float silu_f(float x) {
    return x / (1.0f + expf(-x));
}

// ---------------------------------------------------------------- pre pass
__global__ void __launch_bounds__(256) pre_kernel(const float* __restrict__ delta,
                                                  const float* __restrict__ z) {
    int i = (blockIdx.x * blockDim.x + threadIdx.x) * 4;
    float4 dd = *reinterpret_cast<const float4*>(delta + i);
    float4 zz = *reinterpret_cast<const float4*>(z + i);
    float4 sp, sz;
    sp.x = softplus_f(dd.x); sp.y = softplus_f(dd.y);
    sp.z = softplus_f(dd.z); sp.w = softplus_f(dd.w);
    sz.x = silu_f(zz.x); sz.y = silu_f(zz.y);
    sz.z = silu_f(zz.z); sz.w = silu_f(zz.w);
    *reinterpret_cast<float4*>(g_sp + i) = sp;
    *reinterpret_cast<float4*>(g_sz + i) = sz;
}

// ---------------------------------------------------------- phase 1: local scans
// Block = 16 rows (8 warps x 2 rows) x 1 chunk, all rows in same batch.
// grid.x = (ROWS/16) * CHUNKS = 128 * 16 = 2048
__global__ void __launch_bounds__(256) phase1_kernel(const float* __restrict__ u,
                                                     const float* __restrict__ A,
                                                     const float* __restrict__ B) {
    __shared__ float Bsm[CLEN][PITCH];

    const int tid   = threadIdx.x;
    const int lane  = tid & 31;
    const int warp  = tid >> 5;
    const int n     = lane & 15;
    const int half  = lane >> 4;
    const int rg    = blockIdx.x / CHUNKS;   // row group (0..127)
    const int chunk = blockIdx.x % CHUNKS;
    const int row   = rg * 16 + warp * 2 + half;
    const int b     = row / DDIM;
    const int d     = row - b * DDIM;
    const int t0    = chunk * CLEN;

    const float A2 = A[d * NST + n] * LOG2E;
    const float* __restrict__ sp_r = g_sp + (size_t)row * LEN + t0;
    const float* __restrict__ u_r  = u    + (size_t)row * LEN + t0;
    const float* __restrict__ B_b  = B + (size_t)b * NST * LEN + t0;

    // Stage B tile transposed to [t][n]
    #pragma unroll
    for (int i = tid; i < NST * (CLEN / 4); i += 256) {
        const int nn = i >> 5;
        const int t4 = (i & 31) << 2;
        float4 b4 = *reinterpret_cast<const float4*>(B_b + nn * LEN + t4);
        Bsm[t4 + 0][nn] = b4.x; Bsm[t4 + 1][nn] = b4.y;
        Bsm[t4 + 2][nn] = b4.z; Bsm[t4 + 3][nn] = b4.w;
    }
    __syncthreads();

    float h = 0.0f, ssum = 0.0f;
    #pragma unroll 4
    for (int tj = 0; tj < CLEN; tj += 4) {
        float4 sp4 = *reinterpret_cast<const float4*>(sp_r + tj);
        float4 u4  = *reinterpret_cast<const float4*>(u_r + tj);
        h = fmaf(ex2f(sp4.x * A2), h, (sp4.x * u4.x) * Bsm[tj + 0][n]);
        h = fmaf(ex2f(sp4.y * A2), h, (sp4.y * u4.y) * Bsm[tj + 1][n]);
        h = fmaf(ex2f(sp4.z * A2), h, (sp4.z * u4.z) * Bsm[tj + 2][n]);
        h = fmaf(ex2f(sp4.w * A2), h, (sp4.w * u4.w) * Bsm[tj + 3][n]);
        ssum += (sp4.x + sp4.y) + (sp4.z + sp4.w);
    }

    g_hloc[((size_t)row * CHUNKS + chunk) * NST + n] = h;
    if (n == 0) g_sumsp[row * CHUNKS + chunk] = ssum;
}

// ---------------------------------------------------------- phase 2: chunk combine
// One thread per (row, n): sequential over CHUNKS.
__global__ void __launch_bounds__(256) phase2_kernel(const float* __restrict__ A) {
    const int idx = blockIdx.x * blockDim.x + threadIdx.x;   // 0..ROWS*NST-1
    const int row = idx / NST;
    const int n   = idx - row * NST;
    const int d   = row & (DDIM - 1);
    const float A2 = A[d * NST + n] * LOG2E;

    float H = 0.0f;
    #pragma unroll
    for (int c = 0; c < CHUNKS; c++) {
        g_carry[((size_t)row * CHUNKS + c) * NST + n] = H;
        float P = ex2f(A2 * g_sumsp[row * CHUNKS + c]);
        H = fmaf(P, H, g_hloc[((size_t)row * CHUNKS + c) * NST + n]);
    }
}

// ---------------------------------------------------------- phase 3: full scan + output
// Same block layout as phase 1; h starts from the carry.
__global__ void __launch_bounds__(256) phase3_kernel(const float* __restrict__ u,
                                                     const float* __restrict__ A,
                                                     const float* __restrict__ B,
                                                     const float* __restrict__ C,
                                                     const float* __restrict__ Dv,
                                                     float* __restrict__ y) {
    __shared__ float Bsm[CLEN][PITCH];
    __shared__ float Csm[CLEN][PITCH];

    const int tid   = threadIdx.x;
    const int lane  = tid & 31;
    const int warp  = tid >> 5;
    const int n     = lane & 15;
    const int half  = lane >> 4;
    const int rg    = blockIdx.x / CHUNKS;
    const int chunk = blockIdx.x % CHUNKS;
    const int row   = rg * 16 + warp * 2 + half;
    const int b     = row / DDIM;
    const int d     = row - b * DDIM;
    const int t0    = chunk * CLEN;

    const float A2 = A[d * NST + n] * LOG2E;
    const float Dd = Dv[d];

    const float* __restrict__ sp_r = g_sp + (size_t)row * LEN + t0;
    const float* __restrict__ sz_r = g_sz + (size_t)row * LEN + t0;
    const float* __restrict__ u_r  = u    + (size_t)row * LEN + t0;
    float*       __restrict__ y_r  = y    + (size_t)row * LEN + t0;
    const float* __restrict__ B_b  = B + (size_t)b * NST * LEN + t0;
    const float* __restrict__ C_b  = C + (size_t)b * NST * LEN + t0;

    #pragma unroll
    for (int i = tid; i < NST * (CLEN / 4); i += 256) {
        const int nn = i >> 5;
        const int t4 = (i & 31) << 2;
        float4 b4 = *reinterpret_cast<const float4*>(B_b + nn * LEN + t4);
        float4 c4 = *reinterpret_cast<const float4*>(C_b + nn * LEN + t4);
        Bsm[t4 + 0][nn] = b4.x; Bsm[t4 + 1][nn] = b4.y;
        Bsm[t4 + 2][nn] = b4.z; Bsm[t4 + 3][nn] = b4.w;
        Csm[t4 + 0][nn] = c4.x; Csm[t4 + 1][nn] = c4.y;
        Csm[t4 + 2][nn] = c4.z; Csm[t4 + 3][nn] = c4.w;
    }
    __syncthreads();

    float h = g_carry[((size_t)row * CHUNKS + chunk) * NST + n];

    #pragma unroll 2
    for (int tj = 0; tj < CLEN; tj += 4) {
        float4 sp4 = *reinterpret_cast<const float4*>(sp_r + tj);
        float4 u4  = *reinterpret_cast<const float4*>(u_r + tj);
        float4 sz4 = *reinterpret_cast<const float4*>(sz_r + tj);
        float r0, r1, r2, r3;

        {
            h = fmaf(ex2f(sp4.x * A2), h, (sp4.x * u4.x) * Bsm[tj + 0][n]);
            float p = Csm[tj + 0][n] * h;
            p += __shfl_xor_sync(0xffffffffu, p, 8);
            p += __shfl_xor_sync(0xffffffffu, p, 4);
            p += __shfl_xor_sync(0xffffffffu, p, 2);
            p += __shfl_xor_sync(0xffffffffu, p, 1);
            r0 = (p + u4.x * Dd) * sz4.x;
        }
        {
            h = fmaf(ex2f(sp4.y * A2), h, (sp4.y * u4.y) * Bsm[tj + 1][n]);
            float p = Csm[tj + 1][n] * h;
            p += __shfl_xor_sync(0xffffffffu, p, 8);
            p += __shfl_xor_sync(0xffffffffu, p, 4);
            p += __shfl_xor_sync(0xffffffffu, p, 2);
            p += __shfl_xor_sync(0xffffffffu, p, 1);
            r1 = (p + u4.y * Dd) * sz4.y;
        }
        {
            h = fmaf(ex2f(sp4.z * A2), h, (sp4.z * u4.z) * Bsm[tj + 2][n]);
            float p = Csm[tj + 2][n] * h;
            p += __shfl_xor_sync(0xffffffffu, p, 8);
            p += __shfl_xor_sync(0xffffffffu, p, 4);
            p += __shfl_xor_sync(0xffffffffu, p, 2);
            p += __shfl_xor_sync(0xffffffffu, p, 1);
            r2 = (p + u4.z * Dd) * sz4.z;
        }
        {
            h = fmaf(ex2f(sp4.w * A2), h, (sp4.w * u4.w) * Bsm[tj + 3][n]);
            float p = Csm[tj + 3][n] * h;
            p += __shfl_xor_sync(0xffffffffu, p, 8);
            p += __shfl_xor_sync(0xffffffffu, p, 4);
            p += __shfl_xor_sync(0xffffffffu, p, 2);
            p += __shfl_xor_sync(0xffffffffu, p, 1);
            r3 = (p + u4.w * Dd) * sz4.w;
        }

        if (n == 0) {
            *reinterpret_cast<float4*>(y_r + tj) = make_float4(r0, r1, r2, r3);
        }
    }
}

extern "C" void kernel_launch(void* const* d_in, const int* in_sizes, int n_in,
                              void* d_out, int out_size) {
    // metadata order: u, delta, A, B, C, D, z, delta_softplus
    const float* u     = (const float*)d_in[0];
    const float* delta = (const float*)d_in[1];
    const float* A     = (const float*)d_in[2];
    const float* B     = (const float*)d_in[3];
    const float* C     = (const float*)d_in[4];
    const float* D     = (const float*)d_in[5];
    const float* z     = (const float*)d_in[6];
    float* y = (float*)d_out;

    pre_kernel<<<(ROWS * LEN) / (256 * 4), 256>>>(delta, z);
    phase1_kernel<<<(ROWS / 16) * CHUNKS, 256>>>(u, A, B);
    phase2_kernel<<<(ROWS * NST) / 256, 256>>>(A);
    phase3_kernel<<<(ROWS / 16) * CHUNKS, 256>>>(u, A, B, C, D, y);
}

// round 4
// speedup vs baseline: 2.8772x; 1.7384x over previous
#include <cuda_runtime.h>
#include <math.h>

// Problem shape (fixed by reference setup_inputs)
#define BATCH  2
#define DDIM   1024
#define NST    16
#define LEN    2048
#define ROWS   (BATCH * DDIM)     // 2048
#define CHUNKS 32
#define CLEN   (LEN / CHUNKS)     // 64
#define BPITCH 20                 // smem pitch in floats (80B: 16B-aligned rows, reduced STS conflicts)
#define LOG2E    1.4426950408889634f
#define RCP_LOG2 0.6931471805599453f

// Scratch (no cudaMalloc allowed)
__device__ float g_spt[LEN * ROWS];             // softplus(delta), transposed [t][row]
__device__ float g_ut [LEN * ROWS];             // u, transposed [t][row]
__device__ float g_hloc [ROWS * CHUNKS * NST];  // per-chunk local final state
__device__ float g_sumsp[ROWS * CHUNKS];        // per-chunk sum of softplus
__device__ float g_carry[ROWS * CHUNKS * NST];  // carry-in state per chunk

__device__ __forceinline__ float ex2f(float x) {
    float y;
    asm("ex2.approx.ftz.f32 %0, %1;" : "=f"(y) : "f"(x));
    return y;
}
__device__ __forceinline__ float lg2f(float x) {
    float y;
    asm("lg2.approx.ftz.f32 %0, %1;" : "=f"(y) : "f"(x));
    return y;
}
// softplus(x) = log2(1 + 2^(x*log2e)) / log2e   (guarded for large x)
__device__ __forceinline__ float softplus_f(float x) {
    if (x > 20.0f) return x;
    return lg2f(1.0f + ex2f(x * LOG2E)) * RCP_LOG2;
}
__device__ __forceinline__ float silu_f(float x) {
    float e = ex2f(-x * LOG2E);            // exp(-x)
    return __fdividef(x, 1.0f + e);
}

// ------------------------------------------------------------------ phase 1
// Thread = (row, chunk), all 16 states in registers.
// Block = 128 threads = 128 consecutive rows (same batch), one chunk.
// Grid = (ROWS/128, CHUNKS) = (16, 32).
// Reads delta,u raw; computes softplus; writes sp,u transposed for phase 3;
// produces chunk-final h[16] and sum-of-softplus.
__global__ void __launch_bounds__(128) phase1_kernel(const float* __restrict__ u,
                                                     const float* __restrict__ delta,
                                                     const float* __restrict__ A,
                                                     const float* __restrict__ B) {
    __shared__ float Bsm[CLEN][BPITCH];

    const int tid   = threadIdx.x;
    const int row   = blockIdx.x * 128 + tid;
    const int chunk = blockIdx.y;
    const int b     = row >> 10;          // DDIM = 1024
    const int d     = row & (DDIM - 1);
    const int t0    = chunk * CLEN;

    // Stage B tile [t][n] (all lanes of a warp will broadcast-read it)
    const float* __restrict__ Bb = B + (size_t)b * NST * LEN + t0;
    for (int i = tid; i < NST * (CLEN / 4); i += 128) {
        const int nn = i >> 4;
        const int t4 = (i & 15) << 2;
        float4 v = *reinterpret_cast<const float4*>(Bb + nn * LEN + t4);
        Bsm[t4 + 0][nn] = v.x; Bsm[t4 + 1][nn] = v.y;
        Bsm[t4 + 2][nn] = v.z; Bsm[t4 + 3][nn] = v.w;
    }

    float A2[NST];
    {
        const float4* Ap = reinterpret_cast<const float4*>(A + d * NST);
        #pragma unroll
        for (int q = 0; q < 4; q++) {
            float4 a = Ap[q];
            A2[q * 4 + 0] = a.x * LOG2E; A2[q * 4 + 1] = a.y * LOG2E;
            A2[q * 4 + 2] = a.z * LOG2E; A2[q * 4 + 3] = a.w * LOG2E;
        }
    }
    __syncthreads();

    const float* __restrict__ dp = delta + (size_t)row * LEN + t0;
    const float* __restrict__ up = u     + (size_t)row * LEN + t0;
    float* __restrict__ sptp = g_spt + (size_t)t0 * ROWS + row;
    float* __restrict__ utp  = g_ut  + (size_t)t0 * ROWS + row;

    float h[NST];
    #pragma unroll
    for (int j = 0; j < NST; j++) h[j] = 0.0f;
    float ssum = 0.0f;

    #pragma unroll 1
    for (int tq = 0; tq < CLEN; tq += 4) {
        float4 d4 = *reinterpret_cast<const float4*>(dp + tq);
        float4 u4 = *reinterpret_cast<const float4*>(up + tq);
        float sp[4], uu[4];
        sp[0] = softplus_f(d4.x); sp[1] = softplus_f(d4.y);
        sp[2] = softplus_f(d4.z); sp[3] = softplus_f(d4.w);
        uu[0] = u4.x; uu[1] = u4.y; uu[2] = u4.z; uu[3] = u4.w;

        #pragma unroll
        for (int k = 0; k < 4; k++) {
            const int t = tq + k;
            sptp[(size_t)t * ROWS] = sp[k];
            utp [(size_t)t * ROWS] = uu[k];
            ssum += sp[k];
            const float dbu = sp[k] * uu[k];
            float Bv[NST];
            {
                const float4* Bt = reinterpret_cast<const float4*>(&Bsm[t][0]);
                float4 b0 = Bt[0], b1 = Bt[1], b2 = Bt[2], b3 = Bt[3];
                Bv[0]=b0.x; Bv[1]=b0.y; Bv[2]=b0.z; Bv[3]=b0.w;
                Bv[4]=b1.x; Bv[5]=b1.y; Bv[6]=b1.z; Bv[7]=b1.w;
                Bv[8]=b2.x; Bv[9]=b2.y; Bv[10]=b2.z; Bv[11]=b2.w;
                Bv[12]=b3.x; Bv[13]=b3.y; Bv[14]=b3.z; Bv[15]=b3.w;
            }
            #pragma unroll
            for (int j = 0; j < NST; j++) {
                h[j] = fmaf(ex2f(sp[k] * A2[j]), h[j], dbu * Bv[j]);
            }
        }
    }

    float* __restrict__ hp = g_hloc + ((size_t)row * CHUNKS + chunk) * NST;
    #pragma unroll
    for (int q = 0; q < 4; q++) {
        *reinterpret_cast<float4*>(hp + q * 4) =
            make_float4(h[q*4+0], h[q*4+1], h[q*4+2], h[q*4+3]);
    }
    g_sumsp[row * CHUNKS + chunk] = ssum;
}

// ------------------------------------------------------------------ phase 2
// One thread per (row, n): sequential combine over CHUNKS.
__global__ void __launch_bounds__(256) phase2_kernel(const float* __restrict__ A) {
    const int idx = blockIdx.x * blockDim.x + threadIdx.x;   // 0..ROWS*NST-1
    const int row = idx >> 4;
    const int n   = idx & (NST - 1);
    const int d   = row & (DDIM - 1);
    const float A2 = A[d * NST + n] * LOG2E;

    float H = 0.0f;
    #pragma unroll
    for (int c = 0; c < CHUNKS; c++) {
        g_carry[((size_t)row * CHUNKS + c) * NST + n] = H;
        float P = ex2f(A2 * g_sumsp[row * CHUNKS + c]);
        H = fmaf(P, H, g_hloc[((size_t)row * CHUNKS + c) * NST + n]);
    }
}

// ------------------------------------------------------------------ phase 3
// Same layout as phase 1; h starts from carry; reads sp,u transposed
// (coalesced), z raw; produces y.
__global__ void __launch_bounds__(128) phase3_kernel(const float* __restrict__ A,
                                                     const float* __restrict__ B,
                                                     const float* __restrict__ C,
                                                     const float* __restrict__ Dv,
                                                     const float* __restrict__ z,
                                                     float* __restrict__ y) {
    __shared__ float Bsm[CLEN][BPITCH];
    __shared__ float Csm[CLEN][BPITCH];

    const int tid   = threadIdx.x;
    const int row   = blockIdx.x * 128 + tid;
    const int chunk = blockIdx.y;
    const int b     = row >> 10;
    const int d     = row & (DDIM - 1);
    const int t0    = chunk * CLEN;

    const float* __restrict__ Bb = B + (size_t)b * NST * LEN + t0;
    const float* __restrict__ Cb = C + (size_t)b * NST * LEN + t0;
    for (int i = tid; i < NST * (CLEN / 4); i += 128) {
        const int nn = i >> 4;
        const int t4 = (i & 15) << 2;
        float4 v = *reinterpret_cast<const float4*>(Bb + nn * LEN + t4);
        Bsm[t4 + 0][nn] = v.x; Bsm[t4 + 1][nn] = v.y;
        Bsm[t4 + 2][nn] = v.z; Bsm[t4 + 3][nn] = v.w;
        float4 w = *reinterpret_cast<const float4*>(Cb + nn * LEN + t4);
        Csm[t4 + 0][nn] = w.x; Csm[t4 + 1][nn] = w.y;
        Csm[t4 + 2][nn] = w.z; Csm[t4 + 3][nn] = w.w;
    }

    float A2[NST];
    {
        const float4* Ap = reinterpret_cast<const float4*>(A + d * NST);
        #pragma unroll
        for (int q = 0; q < 4; q++) {
            float4 a = Ap[q];
            A2[q * 4 + 0] = a.x * LOG2E; A2[q * 4 + 1] = a.y * LOG2E;
            A2[q * 4 + 2] = a.z * LOG2E; A2[q * 4 + 3] = a.w * LOG2E;
        }
    }
    const float Dd = Dv[d];

    float h[NST];
    {
        const float4* cp = reinterpret_cast<const float4*>(
            g_carry + ((size_t)row * CHUNKS + chunk) * NST);
        #pragma unroll
        for (int q = 0; q < 4; q++) {
            float4 c4 = cp[q];
            h[q*4+0] = c4.x; h[q*4+1] = c4.y; h[q*4+2] = c4.z; h[q*4+3] = c4.w;
        }
    }
    __syncthreads();

    const float* __restrict__ sptp = g_spt + (size_t)t0 * ROWS + row;
    const float* __restrict__ utp  = g_ut  + (size_t)t0 * ROWS + row;
    const float* __restrict__ zp   = z + (size_t)row * LEN + t0;
    float*       __restrict__ yp   = y + (size_t)row * LEN + t0;

    #pragma unroll 1
    for (int tq = 0; tq < CLEN; tq += 4) {
        float4 z4 = *reinterpret_cast<const float4*>(zp + tq);
        float zz[4] = {z4.x, z4.y, z4.z, z4.w};
        float r[4];

        #pragma unroll
        for (int k = 0; k < 4; k++) {
            const int t = tq + k;
            const float spv = sptp[(size_t)t * ROWS];
            const float uv  = utp [(size_t)t * ROWS];
            const float dbu = spv * uv;

            float Bv[NST], Cv[NST];
            {
                const float4* Bt = reinterpret_cast<const float4*>(&Bsm[t][0]);
                const float4* Ct = reinterpret_cast<const float4*>(&Csm[t][0]);
                #pragma unroll
                for (int q = 0; q < 4; q++) {
                    float4 bb = Bt[q], cc = Ct[q];
                    Bv[q*4+0]=bb.x; Bv[q*4+1]=bb.y; Bv[q*4+2]=bb.z; Bv[q*4+3]=bb.w;
                    Cv[q*4+0]=cc.x; Cv[q*4+1]=cc.y; Cv[q*4+2]=cc.z; Cv[q*4+3]=cc.w;
                }
            }

            float a0 = 0.0f, a1 = 0.0f, a2 = 0.0f, a3 = 0.0f;
            #pragma unroll
            for (int j = 0; j < NST; j += 4) {
                h[j+0] = fmaf(ex2f(spv * A2[j+0]), h[j+0], dbu * Bv[j+0]);
                a0 = fmaf(Cv[j+0], h[j+0], a0);
                h[j+1] = fmaf(ex2f(spv * A2[j+1]), h[j+1], dbu * Bv[j+1]);
                a1 = fmaf(Cv[j+1], h[j+1], a1);
                h[j+2] = fmaf(ex2f(spv * A2[j+2]), h[j+2], dbu * Bv[j+2]);
                a2 = fmaf(Cv[j+2], h[j+2], a2);
                h[j+3] = fmaf(ex2f(spv * A2[j+3]), h[j+3], dbu * Bv[j+3]);
                a3 = fmaf(Cv[j+3], h[j+3], a3);
            }
            const float acc = (a0 + a1) + (a2 + a3);
            r[k] = (acc + uv * Dd) * silu_f(zz[k]);
        }

        *reinterpret_cast<float4*>(yp + tq) = make_float4(r[0], r[1], r[2], r[3]);
    }
}

extern "C" void kernel_launch(void* const* d_in, const int* in_sizes, int n_in,
                              void* d_out, int out_size) {
    // metadata order: u, delta, A, B, C, D, z, delta_softplus
    const float* u     = (const float*)d_in[0];
    const float* delta = (const float*)d_in[1];
    const float* A     = (const float*)d_in[2];
    const float* B     = (const float*)d_in[3];
    const float* C     = (const float*)d_in[4];
    const float* D     = (const float*)d_in[5];
    const float* z     = (const float*)d_in[6];
    float* y = (float*)d_out;

    dim3 grid1(ROWS / 128, CHUNKS);
    phase1_kernel<<<grid1, 128>>>(u, delta, A, B);
    phase2_kernel<<<(ROWS * NST) / 256, 256>>>(A);
    phase3_kernel<<<grid1, 128>>>(A, B, C, D, z, y);
}